// round 14
// baseline (speedup 1.0000x reference)
#include <cuda_runtime.h>
#include <cuda_fp16.h>
#include <math.h>
#include <stdint.h>

#define NN   50000
#define EE   1600000
#define DIN  1024
#define HH   256
#define LL   64
#define CC   4
#define NNZ  (EE + NN)

// ---------------- scratch (device globals: no allocation allowed) ----------
__device__ __half2 g_hA [(size_t)NN * (HH / 2)];    // fp16 h ping
__device__ __half2 g_hB [(size_t)NN * (HH / 2)];    // fp16 h pong
__device__ __half2 g_h0h[(size_t)NN * (HH / 2)];    // fp16 h0
__device__ __half2 g_xh [(size_t)NN * (DIN / 2)];   // fp16 x
__device__ __half2 g_wTh[(size_t)LL * HH * (HH / 2)];  // fp16 W'^T = ((1-b)I + b W)^T
__device__ __half2 g_pWh[(size_t)HH * (DIN / 2)];
__device__ int     g_deg[NN];
__device__ float   g_dinv[NN];
__device__ int     g_rowptr[NN + 1];
__device__ int     g_fill[NN];
__device__ int     g_col[NNZ];
__device__ float   g_val[NNZ];

// ---------------- graph preprocessing ----------------

__global__ void k_init_deg() {
    int i = blockIdx.x * blockDim.x + threadIdx.x;
    if (i < NN) g_deg[i] = 1;
}
__global__ void k_count(const int* __restrict__ dst) {
    int e = blockIdx.x * blockDim.x + threadIdx.x;
    if (e < EE) atomicAdd(&g_deg[dst[e]], 1);
}
__global__ void k_dinv() {
    int i = blockIdx.x * blockDim.x + threadIdx.x;
    if (i < NN) g_dinv[i] = rsqrtf((float)g_deg[i]);
}
__global__ void k_scan() {
    __shared__ int sh[1024];
    __shared__ int carry;
    int tid = threadIdx.x;
    if (tid == 0) { carry = 0; g_rowptr[0] = 0; }
    __syncthreads();
    for (int base = 0; base < NN; base += 1024) {
        int i = base + tid;
        int v = (i < NN) ? g_deg[i] : 0;
        sh[tid] = v;
        __syncthreads();
        for (int off = 1; off < 1024; off <<= 1) {
            int t = (tid >= off) ? sh[tid - off] : 0;
            __syncthreads();
            sh[tid] += t;
            __syncthreads();
        }
        if (i < NN) g_rowptr[i + 1] = carry + sh[tid];
        __syncthreads();
        if (tid == 0) carry += sh[1023];
        __syncthreads();
    }
}
__global__ void k_selfloop() {
    int i = blockIdx.x * blockDim.x + threadIdx.x;
    if (i < NN) {
        int p = g_rowptr[i];
        float d = g_dinv[i];
        g_col[p] = i;
        g_val[p] = d * d;
        g_fill[i] = 1;
    }
}
__global__ void k_fill(const int* __restrict__ src, const int* __restrict__ dst) {
    int e = blockIdx.x * blockDim.x + threadIdx.x;
    if (e < EE) {
        int d = dst[e];
        int s = src[e];
        int p = atomicAdd(&g_fill[d], 1);
        int idx = g_rowptr[d] + p;
        g_col[idx] = s;
        g_val[idx] = g_dinv[s] * g_dinv[d];
    }
}

// weight transpose + residual fold: g_wTh[l][n][k] = fp16((1-b)I[k][n] + b*W[l][k][n])
__global__ void k_transpose_w(const float* __restrict__ W) {
    __shared__ float t[32][33];
    int l = blockIdx.z;
    float beta = logf(0.5f / (float)(l + 1) + 1.0f);
    int n0 = blockIdx.x * 32, k0 = blockIdx.y * 32;
    const float* Wl = W + (size_t)l * HH * HH;
    __half* out = reinterpret_cast<__half*>(g_wTh) + (size_t)l * HH * HH;
#pragma unroll
    for (int dy = 0; dy < 32; dy += 8)
        t[threadIdx.y + dy][threadIdx.x] = Wl[(size_t)(k0 + threadIdx.y + dy) * HH + n0 + threadIdx.x];
    __syncthreads();
#pragma unroll
    for (int dy = 0; dy < 32; dy += 8) {
        int n = n0 + threadIdx.y + dy;
        int k = k0 + threadIdx.x;
        float v = beta * t[threadIdx.x][threadIdx.y + dy];
        if (n == k) v += 1.0f - beta;
        out[(size_t)n * HH + k] = __float2half_rn(v);
    }
}

// projW transpose to fp16
__global__ void k_transpose_pw(const float* __restrict__ PW) {
    __shared__ float t[32][33];
    int n0 = blockIdx.x * 32, k0 = blockIdx.y * 32;
    __half* out = reinterpret_cast<__half*>(g_pWh);
#pragma unroll
    for (int dy = 0; dy < 32; dy += 8)
        t[threadIdx.y + dy][threadIdx.x] = PW[(size_t)(k0 + threadIdx.y + dy) * HH + n0 + threadIdx.x];
    __syncthreads();
#pragma unroll
    for (int dy = 0; dy < 32; dy += 8)
        out[(size_t)(n0 + threadIdx.y + dy) * DIN + k0 + threadIdx.x] =
            __float2half_rn(t[threadIdx.x][threadIdx.y + dy]);
}

// x -> fp16
__global__ void k_x2h(const float* __restrict__ x) {
    int i = blockIdx.x * blockDim.x + threadIdx.x;
    const int total = NN * DIN / 4;
    if (i < total) {
        float4 v = reinterpret_cast<const float4*>(x)[i];
        g_xh[i * 2 + 0] = __floats2half2_rn(v.x, v.y);
        g_xh[i * 2 + 1] = __floats2half2_rn(v.z, v.w);
    }
}

// ---------------- MMA / async helpers ----------------

#define MMA_F16(ACC, A0, A1, A2, A3, B0, B1)                                 \
    asm volatile(                                                            \
        "mma.sync.aligned.m16n8k16.row.col.f32.f16.f16.f32 "                \
        "{%0,%1,%2,%3}, {%4,%5,%6,%7}, {%8,%9}, {%0,%1,%2,%3};"             \
        : "+f"((ACC)[0]), "+f"((ACC)[1]), "+f"((ACC)[2]), "+f"((ACC)[3])    \
        : "r"(A0), "r"(A1), "r"(A2), "r"(A3), "r"(B0), "r"(B1))

#define LDSM_X4(R0, R1, R2, R3, ADDR)                                        \
    asm volatile(                                                            \
        "ldmatrix.sync.aligned.m8n8.x4.shared.b16 {%0,%1,%2,%3}, [%4];"     \
        : "=r"(R0), "=r"(R1), "=r"(R2), "=r"(R3) : "r"(ADDR))

__device__ __forceinline__ void cp_async16(uint32_t saddr, const void* g, int srcBytes) {
    asm volatile("cp.async.ca.shared.global [%0], [%1], 16, %2;"
                 :: "r"(saddr), "l"(g), "r"(srcBytes) : "memory");
}
#define CP_COMMIT() asm volatile("cp.async.commit_group;" ::: "memory")
#define CP_WAIT0()  asm volatile("cp.async.wait_group 0;" ::: "memory")

// ---------------- FUSED layer: gather -> s-tile (SMEM) -> GEMM -> h ---------
// 512 threads, 1 CTA/SM. Ping-pong h buffers: read hin, write hout (disjoint).
// SMEM: Stile [128][132] h2 + 2 x Bchunk [256][36] h2 = 138 KB.

#define SPAD 132
#define BPAD 36
#define STILE_H2 (128 * SPAD)
#define BCH_H2   (256 * BPAD)
#define FUSED_SMEM ((STILE_H2 + 2 * BCH_H2) * 4)

__global__ __launch_bounds__(512, 1) void k_fused(int layer, int first) {
    extern __shared__ __half2 dsm[];
    __half2* Stile   = dsm;
    __half2* Bbuf[2] = { dsm + STILE_H2, dsm + STILE_H2 + BCH_H2 };

    const __half2* __restrict__ wTl = g_wTh + (size_t)layer * HH * 128;
    const __half2* __restrict__ hin = first ? g_h0h : ((layer & 1) ? g_hA : g_hB);
    __half2* __restrict__ hout = (layer & 1) ? g_hB : g_hA;

    int tid = threadIdx.x;
    int rowBase = blockIdx.x * 128;

    auto prefetchB = [&](int ch, int st) {
        int k2 = ch * 32;
#pragma unroll
        for (int i = 0; i < 4; i++) {
            int idx = tid + i * 512;          // 0..2047
            int r = idx >> 3;                 // 0..255
            int c2 = (idx & 7) * 4;
            uint32_t bdst = (uint32_t)__cvta_generic_to_shared(Bbuf[st] + r * BPAD + c2);
            cp_async16(bdst, wTl + (size_t)r * 128 + k2 + c2, 16);
        }
        CP_COMMIT();
    };

    // B chunk 0 streams in while we gather
    prefetchB(0, 0);

    // ---- gather phase: 4 rows in flight (128 threads per row) ----
    int rg  = tid >> 7;      // row group 0..3
    int cch = tid & 127;     // h2 channel
    for (int rt = rg; rt < 128; rt += 4) {
        int row = rowBase + rt;
        float ax = 0.f, ay = 0.f;
        if (row < NN) {
            int s0 = g_rowptr[row];
            int s1 = g_rowptr[row + 1];
            int e = s0;
            for (; e + 4 <= s1; e += 4) {
                int c0 = g_col[e + 0], c1 = g_col[e + 1], c2 = g_col[e + 2], c3 = g_col[e + 3];
                float v0 = g_val[e + 0], v1 = g_val[e + 1], v2 = g_val[e + 2], v3 = g_val[e + 3];
                float2 f0 = __half22float2(hin[(size_t)c0 * 128 + cch]);
                float2 f1 = __half22float2(hin[(size_t)c1 * 128 + cch]);
                float2 f2 = __half22float2(hin[(size_t)c2 * 128 + cch]);
                float2 f3 = __half22float2(hin[(size_t)c3 * 128 + cch]);
                ax = fmaf(v0, f0.x, ax); ay = fmaf(v0, f0.y, ay);
                ax = fmaf(v1, f1.x, ax); ay = fmaf(v1, f1.y, ay);
                ax = fmaf(v2, f2.x, ax); ay = fmaf(v2, f2.y, ay);
                ax = fmaf(v3, f3.x, ax); ay = fmaf(v3, f3.y, ay);
            }
            for (; e < s1; e++) {
                float2 f = __half22float2(hin[(size_t)g_col[e] * 128 + cch]);
                float v = g_val[e];
                ax = fmaf(v, f.x, ax);
                ay = fmaf(v, f.y, ay);
            }
            float2 h0v = __half22float2(g_h0h[(size_t)row * 128 + cch]);
            ax = 0.8f * ax + 0.2f * h0v.x;
            ay = 0.8f * ay + 0.2f * h0v.y;
        }
        Stile[rt * SPAD + cch] = __floats2half2_rn(ax, ay);
    }
    __syncthreads();

    // ---- GEMM phase: 16 warps, warp tile 32x64, 4 K-chunks ----
    int wid = tid >> 5;
    int lane = tid & 31;
    int quadRow = lane >> 2;
    int quadCol = lane & 3;
    int warpM = wid >> 2;          // 0..3
    int warpN = wid & 3;           // 0..3
    int mRow = warpM * 32;
    int nBase = warpN * 64;
    int lt = lane >> 3;
    int li = lane & 7;

    float acc[2][8][4];
#pragma unroll
    for (int i = 0; i < 2; i++)
#pragma unroll
        for (int j = 0; j < 8; j++)
#pragma unroll
            for (int k = 0; k < 4; k++) acc[i][j][k] = 0.f;

    for (int ch = 0; ch < 4; ch++) {
        int st = ch & 1;
        CP_WAIT0();
        __syncthreads();
        if (ch < 3) prefetchB(ch + 1, st ^ 1);
        __half2* Bs = Bbuf[st];
        int kbase = ch * 32;   // A h2 offset for this chunk
#pragma unroll
        for (int kk2 = 0; kk2 < 32; kk2 += 8) {
            uint32_t a[2][4];
#pragma unroll
            for (int ma = 0; ma < 2; ma++) {
                uint32_t addr = (uint32_t)__cvta_generic_to_shared(
                    Stile + (mRow + ma * 16 + (lt & 1) * 8 + li) * SPAD + kbase + kk2 + (lt >> 1) * 4);
                LDSM_X4(a[ma][0], a[ma][1], a[ma][2], a[ma][3], addr);
            }
            uint32_t b[8][2];
#pragma unroll
            for (int nb = 0; nb < 8; nb += 2) {
                uint32_t addr = (uint32_t)__cvta_generic_to_shared(
                    Bs + (nBase + nb * 8 + (lt >> 1) * 8 + li) * BPAD + kk2 + (lt & 1) * 4);
                uint32_t r0, r1, r2, r3;
                LDSM_X4(r0, r1, r2, r3, addr);
                b[nb][0] = r0; b[nb][1] = r1;
                b[nb + 1][0] = r2; b[nb + 1][1] = r3;
            }
#pragma unroll
            for (int nb = 0; nb < 8; nb++)
#pragma unroll
                for (int ma = 0; ma < 2; ma++)
                    MMA_F16(acc[ma][nb], a[ma][0], a[ma][1], a[ma][2], a[ma][3],
                            b[nb][0], b[nb][1]);
        }
        __syncthreads();
    }

    // epilogue: h = relu(acc) -> fp16 (disjoint hout buffer; no race)
#pragma unroll
    for (int ma = 0; ma < 2; ma++) {
        int r0 = rowBase + mRow + ma * 16 + quadRow;
        int r1 = r0 + 8;
#pragma unroll
        for (int nb = 0; nb < 8; nb++) {
            int c = nBase + nb * 8 + quadCol * 2;
            if (r0 < NN)
                hout[(size_t)r0 * 128 + (c >> 1)] = __floats2half2_rn(
                    fmaxf(acc[ma][nb][0], 0.f), fmaxf(acc[ma][nb][1], 0.f));
            if (r1 < NN)
                hout[(size_t)r1 * 128 + (c >> 1)] = __floats2half2_rn(
                    fmaxf(acc[ma][nb][2], 0.f), fmaxf(acc[ma][nb][3], 0.f));
        }
    }
}

// ---------------- projection GEMM fp16 (pipelined) -----

#define TPAD 36
#define STAGE_H2 (128 * TPAD)
#define GEMM_SMEM (4 * STAGE_H2 * 4)

__global__ __launch_bounds__(256, 2) void k_gemm_proj(const float* __restrict__ bias) {
    extern __shared__ __half2 dsm[];
    __half2* Abuf[2] = { dsm, dsm + STAGE_H2 };
    __half2* Bbuf[2] = { dsm + 2 * STAGE_H2, dsm + 3 * STAGE_H2 };

    int tid = threadIdx.x;
    int wid = tid >> 5;
    int lane = tid & 31;
    int quadRow = lane >> 2;
    int quadCol = lane & 3;
    int warpM = wid >> 1;
    int warpN = wid & 1;
    int mRow = warpM * 32;
    int nBase = warpN * 64;
    int rowBase = blockIdx.x * 128;
    int colBase = blockIdx.y * 128;

    int lt = lane >> 3;
    int li = lane & 7;

    float acc[2][8][4];
#pragma unroll
    for (int i = 0; i < 2; i++)
#pragma unroll
        for (int j = 0; j < 8; j++)
#pragma unroll
            for (int k = 0; k < 4; k++) acc[i][j][k] = 0.f;

    auto prefetch = [&](int ch, int st) {
        int k2 = ch * 32;
#pragma unroll
        for (int i = 0; i < 4; i++) {
            int idx = tid + i * 256;
            int r = idx >> 3;
            int c2 = (idx & 7) * 4;
            int gr = rowBase + r;
            uint32_t adst = (uint32_t)__cvta_generic_to_shared(Abuf[st] + r * TPAD + c2);
            cp_async16(adst, g_xh + (size_t)gr * 512 + k2 + c2, gr < NN ? 16 : 0);
            uint32_t bdst = (uint32_t)__cvta_generic_to_shared(Bbuf[st] + r * TPAD + c2);
            cp_async16(bdst, g_pWh + (size_t)(colBase + r) * 512 + k2 + c2, 16);
        }
        CP_COMMIT();
    };

    prefetch(0, 0);
    for (int ch = 0; ch < 16; ch++) {
        int st = ch & 1;
        CP_WAIT0();
        __syncthreads();
        if (ch < 15) prefetch(ch + 1, st ^ 1);
        __half2* As = Abuf[st];
        __half2* Bs = Bbuf[st];
#pragma unroll
        for (int kk2 = 0; kk2 < 32; kk2 += 8) {
            uint32_t a[2][4];
#pragma unroll
            for (int ma = 0; ma < 2; ma++) {
                uint32_t addr = (uint32_t)__cvta_generic_to_shared(
                    As + (mRow + ma * 16 + (lt & 1) * 8 + li) * TPAD + kk2 + (lt >> 1) * 4);
                LDSM_X4(a[ma][0], a[ma][1], a[ma][2], a[ma][3], addr);
            }
            uint32_t b[8][2];
#pragma unroll
            for (int nb = 0; nb < 8; nb += 2) {
                uint32_t addr = (uint32_t)__cvta_generic_to_shared(
                    Bs + (nBase + nb * 8 + (lt >> 1) * 8 + li) * TPAD + kk2 + (lt & 1) * 4);
                uint32_t r0, r1, r2, r3;
                LDSM_X4(r0, r1, r2, r3, addr);
                b[nb][0] = r0; b[nb][1] = r1;
                b[nb + 1][0] = r2; b[nb + 1][1] = r3;
            }
#pragma unroll
            for (int nb = 0; nb < 8; nb++)
#pragma unroll
                for (int ma = 0; ma < 2; ma++)
                    MMA_F16(acc[ma][nb], a[ma][0], a[ma][1], a[ma][2], a[ma][3],
                            b[nb][0], b[nb][1]);
        }
        __syncthreads();
    }

#pragma unroll
    for (int ma = 0; ma < 2; ma++) {
        int r0 = rowBase + mRow + ma * 16 + quadRow;
        int r1 = r0 + 8;
#pragma unroll
        for (int nb = 0; nb < 8; nb++) {
            int c = colBase + nBase + nb * 8 + quadCol * 2;
            float bx = bias[c], by = bias[c + 1];
            if (r0 < NN)
                g_h0h[(size_t)r0 * 128 + (c >> 1)] =
                    __floats2half2_rn(acc[ma][nb][0] + bx, acc[ma][nb][1] + by);
            if (r1 < NN)
                g_h0h[(size_t)r1 * 128 + (c >> 1)] =
                    __floats2half2_rn(acc[ma][nb][2] + bx, acc[ma][nb][3] + by);
        }
    }
}

// ---------------- classifier (reads final h buffer) ----------------
__global__ void k_cls(const float* __restrict__ Wc, const float* __restrict__ bc,
                      float* __restrict__ out) {
    int gw   = (blockIdx.x * blockDim.x + threadIdx.x) >> 5;
    int lane = threadIdx.x & 31;
    if (gw >= NN) return;
    // last layer index LL-1 = 63 (odd) writes g_hB
    const __half2* hr = g_hB + (size_t)gw * 128;
    float a0 = 0.f, a1 = 0.f, a2 = 0.f, a3 = 0.f;
    for (int k2 = lane; k2 < 128; k2 += 32) {
        float2 hv = __half22float2(hr[k2]);
        const float* w0 = Wc + (k2 * 2) * CC;
        a0 = fmaf(hv.x, w0[0], a0); a1 = fmaf(hv.x, w0[1], a1);
        a2 = fmaf(hv.x, w0[2], a2); a3 = fmaf(hv.x, w0[3], a3);
        a0 = fmaf(hv.y, w0[4], a0); a1 = fmaf(hv.y, w0[5], a1);
        a2 = fmaf(hv.y, w0[6], a2); a3 = fmaf(hv.y, w0[7], a3);
    }
#pragma unroll
    for (int off = 16; off; off >>= 1) {
        a0 += __shfl_down_sync(0xffffffffu, a0, off);
        a1 += __shfl_down_sync(0xffffffffu, a1, off);
        a2 += __shfl_down_sync(0xffffffffu, a2, off);
        a3 += __shfl_down_sync(0xffffffffu, a3, off);
    }
    if (lane == 0) {
        out[gw * CC + 0] = a0 + bc[0];
        out[gw * CC + 1] = a1 + bc[1];
        out[gw * CC + 2] = a2 + bc[2];
        out[gw * CC + 3] = a3 + bc[3];
    }
}

// ---------------- launch ----------------

extern "C" void kernel_launch(void* const* d_in, const int* in_sizes, int n_in,
                              void* d_out, int out_size) {
    const float* x     = (const float*)d_in[0];
    const int*   ei    = (const int*)  d_in[1];
    const float* projW = (const float*)d_in[2];
    const float* projb = (const float*)d_in[3];
    const float* wts   = (const float*)d_in[4];
    const float* clsW  = (const float*)d_in[5];
    const float* clsb  = (const float*)d_in[6];
    float* out = (float*)d_out;

    const int* src = ei;
    const int* dst = ei + EE;

    static int attrDone = 0;
    if (!attrDone) {
        cudaFuncSetAttribute(k_fused, cudaFuncAttributeMaxDynamicSharedMemorySize, FUSED_SMEM);
        cudaFuncSetAttribute(k_gemm_proj, cudaFuncAttributeMaxDynamicSharedMemorySize, GEMM_SMEM);
        attrDone = 1;
    }

    k_init_deg<<<(NN + 255) / 256, 256>>>();
    k_count   <<<(EE + 255) / 256, 256>>>(dst);
    k_dinv    <<<(NN + 255) / 256, 256>>>();
    k_scan    <<<1, 1024>>>();
    k_selfloop<<<(NN + 255) / 256, 256>>>();
    k_fill    <<<(EE + 255) / 256, 256>>>(src, dst);

    dim3 tg(HH / 32, HH / 32, LL);
    k_transpose_w<<<tg, dim3(32, 8)>>>(wts);
    dim3 pg(HH / 32, DIN / 32);
    k_transpose_pw<<<pg, dim3(32, 8)>>>(projW);
    k_x2h<<<(NN * DIN / 4 + 255) / 256, 256>>>(x);

    dim3 gg((NN + 127) / 128, 2);
    k_gemm_proj<<<gg, 256, GEMM_SMEM>>>(projb);

    int fusedGrid = (NN + 127) / 128;
    for (int l = 0; l < LL; l++)
        k_fused<<<fusedGrid, 512, FUSED_SMEM>>>(l, l == 0 ? 1 : 0);

    k_cls<<<(NN * 32 + 255) / 256, 256>>>(clsW, clsb, out);
}

// round 15
// speedup vs baseline: 2.9442x; 2.9442x over previous
#include <cuda_runtime.h>
#include <cuda_fp16.h>
#include <math.h>
#include <stdint.h>

#define NN   50000
#define EE   1600000
#define DIN  1024
#define HH   256
#define LL   64
#define CC   4
#define NNZ  (EE + NN)

// ---------------- scratch (device globals: no allocation allowed) ----------
__device__ __half2 g_hh [(size_t)NN * (HH / 2)];    // fp16 h
__device__ __half2 g_h0h[(size_t)NN * (HH / 2)];    // fp16 h0
__device__ __half2 g_sh [(size_t)NN * (HH / 2)];    // fp16 s
__device__ __half2 g_xh [(size_t)NN * (DIN / 2)];   // fp16 x
__device__ __half2 g_wTh[(size_t)LL * HH * (HH / 2)];  // fp16 W'^T = ((1-b)I + b W)^T
__device__ __half2 g_pWh[(size_t)HH * (DIN / 2)];
__device__ int     g_deg[NN];
__device__ float   g_dinv[NN];
__device__ int     g_rowptr[NN + 1];
__device__ int     g_fill[NN];
__device__ int     g_col[NNZ];
__device__ float   g_val[NNZ];

// ---------------- graph preprocessing ----------------

__global__ void k_init_deg() {
    int i = blockIdx.x * blockDim.x + threadIdx.x;
    if (i < NN) g_deg[i] = 1;
}
__global__ void k_count(const int* __restrict__ dst) {
    int e = blockIdx.x * blockDim.x + threadIdx.x;
    if (e < EE) atomicAdd(&g_deg[dst[e]], 1);
}
__global__ void k_dinv() {
    int i = blockIdx.x * blockDim.x + threadIdx.x;
    if (i < NN) g_dinv[i] = rsqrtf((float)g_deg[i]);
}
__global__ void k_scan() {
    __shared__ int sh[1024];
    __shared__ int carry;
    int tid = threadIdx.x;
    if (tid == 0) { carry = 0; g_rowptr[0] = 0; }
    __syncthreads();
    for (int base = 0; base < NN; base += 1024) {
        int i = base + tid;
        int v = (i < NN) ? g_deg[i] : 0;
        sh[tid] = v;
        __syncthreads();
        for (int off = 1; off < 1024; off <<= 1) {
            int t = (tid >= off) ? sh[tid - off] : 0;
            __syncthreads();
            sh[tid] += t;
            __syncthreads();
        }
        if (i < NN) g_rowptr[i + 1] = carry + sh[tid];
        __syncthreads();
        if (tid == 0) carry += sh[1023];
        __syncthreads();
    }
}
__global__ void k_selfloop() {
    int i = blockIdx.x * blockDim.x + threadIdx.x;
    if (i < NN) {
        int p = g_rowptr[i];
        float d = g_dinv[i];
        g_col[p] = i;
        g_val[p] = d * d;
        g_fill[i] = 1;
    }
}
__global__ void k_fill(const int* __restrict__ src, const int* __restrict__ dst) {
    int e = blockIdx.x * blockDim.x + threadIdx.x;
    if (e < EE) {
        int d = dst[e];
        int s = src[e];
        int p = atomicAdd(&g_fill[d], 1);
        int idx = g_rowptr[d] + p;
        g_col[idx] = s;
        g_val[idx] = g_dinv[s] * g_dinv[d];
    }
}

// weight transpose + residual fold: g_wTh[l][n][k] = fp16((1-b)I[k][n] + b*W[l][k][n])
__global__ void k_transpose_w(const float* __restrict__ W) {
    __shared__ float t[32][33];
    int l = blockIdx.z;
    float beta = logf(0.5f / (float)(l + 1) + 1.0f);
    int n0 = blockIdx.x * 32, k0 = blockIdx.y * 32;
    const float* Wl = W + (size_t)l * HH * HH;
    __half* out = reinterpret_cast<__half*>(g_wTh) + (size_t)l * HH * HH;
#pragma unroll
    for (int dy = 0; dy < 32; dy += 8)
        t[threadIdx.y + dy][threadIdx.x] = Wl[(size_t)(k0 + threadIdx.y + dy) * HH + n0 + threadIdx.x];
    __syncthreads();
#pragma unroll
    for (int dy = 0; dy < 32; dy += 8) {
        int n = n0 + threadIdx.y + dy;
        int k = k0 + threadIdx.x;
        float v = beta * t[threadIdx.x][threadIdx.y + dy];
        if (n == k) v += 1.0f - beta;
        out[(size_t)n * HH + k] = __float2half_rn(v);
    }
}

// projW transpose to fp16
__global__ void k_transpose_pw(const float* __restrict__ PW) {
    __shared__ float t[32][33];
    int n0 = blockIdx.x * 32, k0 = blockIdx.y * 32;
    __half* out = reinterpret_cast<__half*>(g_pWh);
#pragma unroll
    for (int dy = 0; dy < 32; dy += 8)
        t[threadIdx.y + dy][threadIdx.x] = PW[(size_t)(k0 + threadIdx.y + dy) * HH + n0 + threadIdx.x];
    __syncthreads();
#pragma unroll
    for (int dy = 0; dy < 32; dy += 8)
        out[(size_t)(n0 + threadIdx.y + dy) * DIN + k0 + threadIdx.x] =
            __float2half_rn(t[threadIdx.x][threadIdx.y + dy]);
}

// x -> fp16
__global__ void k_x2h(const float* __restrict__ x) {
    int i = blockIdx.x * blockDim.x + threadIdx.x;
    const int total = NN * DIN / 4;
    if (i < total) {
        float4 v = reinterpret_cast<const float4*>(x)[i];
        g_xh[i * 2 + 0] = __floats2half2_rn(v.x, v.y);
        g_xh[i * 2 + 1] = __floats2half2_rn(v.z, v.w);
    }
}

// ---------------- SpMM: s_fp16 = 0.8 * (A_hat @ h) + 0.2 * h0 (all fp16) ----
__global__ __launch_bounds__(128) void k_spmm(int first) {
    const __half2* __restrict__ hin = first ? g_h0h : g_hh;
    int row = blockIdx.x;
    int tid = threadIdx.x;
    int s0 = g_rowptr[row];
    int s1 = g_rowptr[row + 1];
    __shared__ int   scol[64];
    __shared__ float sval[64];
    float accx = 0.f, accy = 0.f;
    for (int e0 = s0; e0 < s1; e0 += 64) {
        int nE = min(64, s1 - e0);
        __syncthreads();
        if (tid < nE) { scol[tid] = g_col[e0 + tid]; sval[tid] = g_val[e0 + tid]; }
        __syncthreads();
        int i = 0;
        for (; i + 4 <= nE; i += 4) {
            float2 f0 = __half22float2(hin[(size_t)scol[i + 0] * 128 + tid]);
            float2 f1 = __half22float2(hin[(size_t)scol[i + 1] * 128 + tid]);
            float2 f2 = __half22float2(hin[(size_t)scol[i + 2] * 128 + tid]);
            float2 f3 = __half22float2(hin[(size_t)scol[i + 3] * 128 + tid]);
            accx = fmaf(sval[i + 0], f0.x, accx); accy = fmaf(sval[i + 0], f0.y, accy);
            accx = fmaf(sval[i + 1], f1.x, accx); accy = fmaf(sval[i + 1], f1.y, accy);
            accx = fmaf(sval[i + 2], f2.x, accx); accy = fmaf(sval[i + 2], f2.y, accy);
            accx = fmaf(sval[i + 3], f3.x, accx); accy = fmaf(sval[i + 3], f3.y, accy);
        }
        for (; i < nE; i++) {
            float2 f = __half22float2(hin[(size_t)scol[i] * 128 + tid]);
            accx = fmaf(sval[i], f.x, accx);
            accy = fmaf(sval[i], f.y, accy);
        }
    }
    float2 h0v = __half22float2(g_h0h[(size_t)row * 128 + tid]);
    g_sh[(size_t)row * 128 + tid] =
        __floats2half2_rn(0.8f * accx + 0.2f * h0v.x, 0.8f * accy + 0.2f * h0v.y);
}

// ---------------- MMA / async helpers ----------------

#define MMA_F16(ACC, A0, A1, A2, A3, B0, B1)                                 \
    asm volatile(                                                            \
        "mma.sync.aligned.m16n8k16.row.col.f32.f16.f16.f32 "                \
        "{%0,%1,%2,%3}, {%4,%5,%6,%7}, {%8,%9}, {%0,%1,%2,%3};"             \
        : "+f"((ACC)[0]), "+f"((ACC)[1]), "+f"((ACC)[2]), "+f"((ACC)[3])    \
        : "r"(A0), "r"(A1), "r"(A2), "r"(A3), "r"(B0), "r"(B1))

#define LDSM_X4(R0, R1, R2, R3, ADDR)                                        \
    asm volatile(                                                            \
        "ldmatrix.sync.aligned.m8n8.x4.shared.b16 {%0,%1,%2,%3}, [%4];"     \
        : "=r"(R0), "=r"(R1), "=r"(R2), "=r"(R3) : "r"(ADDR))

__device__ __forceinline__ void cp_async16(uint32_t saddr, const void* g, int srcBytes) {
    asm volatile("cp.async.ca.shared.global [%0], [%1], 16, %2;"
                 :: "r"(saddr), "l"(g), "r"(srcBytes) : "memory");
}
#define CP_COMMIT() asm volatile("cp.async.commit_group;" ::: "memory")
#define CP_WAIT0()  asm volatile("cp.async.wait_group 0;" ::: "memory")

#define TPAD 36
#define A_ST (128 * TPAD)                 // h2 per A stage
#define B_ST (256 * TPAD)                 // h2 per B stage
#define MMA_SMEM ((2 * A_ST + 2 * B_ST) * 4)   // 110592 B

// layer GEMM single-slab: h = relu(s @ W'), full N=256 per CTA.
// 512 threads, 16 warps (4x4), warp tile 32x64, 4 K-chunks of 32 h2, pipelined.
__global__ __launch_bounds__(512, 1) void k_gemm_mma(int layer) {
    extern __shared__ __half2 dsm[];
    __half2* Abuf[2] = { dsm, dsm + A_ST };
    __half2* Bbuf[2] = { dsm + 2 * A_ST, dsm + 2 * A_ST + B_ST };

    const __half2* __restrict__ wTl = g_wTh + (size_t)layer * HH * 128;

    int tid = threadIdx.x;
    int wid = tid >> 5;
    int lane = tid & 31;
    int quadRow = lane >> 2;
    int quadCol = lane & 3;
    int warpM = wid >> 2;          // 0..3
    int warpN = wid & 3;           // 0..3
    int mRow = warpM * 32;
    int nBase = warpN * 64;
    int rowBase = blockIdx.x * 128;
    int lt = lane >> 3;
    int li = lane & 7;

    float acc[2][8][4];
#pragma unroll
    for (int i = 0; i < 2; i++)
#pragma unroll
        for (int j = 0; j < 8; j++)
#pragma unroll
            for (int k = 0; k < 4; k++) acc[i][j][k] = 0.f;

    auto prefetch = [&](int ch, int st) {
        int k2 = ch * 32;
        // A: 128 rows x 32 h2 = 1024 float4 -> 2 per thread
#pragma unroll
        for (int i = 0; i < 2; i++) {
            int idx = tid + i * 512;
            int r = idx >> 3;
            int c2 = (idx & 7) * 4;
            int gr = rowBase + r;
            uint32_t adst = (uint32_t)__cvta_generic_to_shared(Abuf[st] + r * TPAD + c2);
            cp_async16(adst, g_sh + (size_t)gr * 128 + k2 + c2, gr < NN ? 16 : 0);
        }
        // B: 256 rows x 32 h2 = 2048 float4 -> 4 per thread
#pragma unroll
        for (int i = 0; i < 4; i++) {
            int idx = tid + i * 512;
            int r = idx >> 3;
            int c2 = (idx & 7) * 4;
            uint32_t bdst = (uint32_t)__cvta_generic_to_shared(Bbuf[st] + r * TPAD + c2);
            cp_async16(bdst, wTl + (size_t)r * 128 + k2 + c2, 16);
        }
        CP_COMMIT();
    };

    prefetch(0, 0);
    for (int ch = 0; ch < 4; ch++) {
        int st = ch & 1;
        CP_WAIT0();
        __syncthreads();
        if (ch < 3) prefetch(ch + 1, st ^ 1);
        __half2* As = Abuf[st];
        __half2* Bs = Bbuf[st];
#pragma unroll
        for (int kk2 = 0; kk2 < 32; kk2 += 8) {
            uint32_t a[2][4];
#pragma unroll
            for (int ma = 0; ma < 2; ma++) {
                uint32_t addr = (uint32_t)__cvta_generic_to_shared(
                    As + (mRow + ma * 16 + (lt & 1) * 8 + li) * TPAD + kk2 + (lt >> 1) * 4);
                LDSM_X4(a[ma][0], a[ma][1], a[ma][2], a[ma][3], addr);
            }
            uint32_t b[8][2];
#pragma unroll
            for (int nb = 0; nb < 8; nb += 2) {
                uint32_t addr = (uint32_t)__cvta_generic_to_shared(
                    Bs + (nBase + nb * 8 + (lt >> 1) * 8 + li) * TPAD + kk2 + (lt & 1) * 4);
                uint32_t r0, r1, r2, r3;
                LDSM_X4(r0, r1, r2, r3, addr);
                b[nb][0] = r0; b[nb][1] = r1;
                b[nb + 1][0] = r2; b[nb + 1][1] = r3;
            }
#pragma unroll
            for (int nb = 0; nb < 8; nb++)
#pragma unroll
                for (int ma = 0; ma < 2; ma++)
                    MMA_F16(acc[ma][nb], a[ma][0], a[ma][1], a[ma][2], a[ma][3],
                            b[nb][0], b[nb][1]);
        }
        __syncthreads();
    }

    // epilogue: h = relu(acc) -> fp16
#pragma unroll
    for (int ma = 0; ma < 2; ma++) {
        int r0 = rowBase + mRow + ma * 16 + quadRow;
        int r1 = r0 + 8;
#pragma unroll
        for (int nb = 0; nb < 8; nb++) {
            int c = nBase + nb * 8 + quadCol * 2;
            if (r0 < NN)
                g_hh[(size_t)r0 * 128 + (c >> 1)] = __floats2half2_rn(
                    fmaxf(acc[ma][nb][0], 0.f), fmaxf(acc[ma][nb][1], 0.f));
            if (r1 < NN)
                g_hh[(size_t)r1 * 128 + (c >> 1)] = __floats2half2_rn(
                    fmaxf(acc[ma][nb][2], 0.f), fmaxf(acc[ma][nb][3], 0.f));
        }
    }
}

// ---------------- projection GEMM fp16 (pipelined, 256 threads) -----

#define STAGE_H2 (128 * TPAD)
#define GEMM_SMEM (4 * STAGE_H2 * 4)

__global__ __launch_bounds__(256, 2) void k_gemm_proj(const float* __restrict__ bias) {
    extern __shared__ __half2 dsm[];
    __half2* Abuf[2] = { dsm, dsm + STAGE_H2 };
    __half2* Bbuf[2] = { dsm + 2 * STAGE_H2, dsm + 3 * STAGE_H2 };

    int tid = threadIdx.x;
    int wid = tid >> 5;
    int lane = tid & 31;
    int quadRow = lane >> 2;
    int quadCol = lane & 3;
    int warpM = wid >> 1;
    int warpN = wid & 1;
    int mRow = warpM * 32;
    int nBase = warpN * 64;
    int rowBase = blockIdx.x * 128;
    int colBase = blockIdx.y * 128;

    int lt = lane >> 3;
    int li = lane & 7;

    float acc[2][8][4];
#pragma unroll
    for (int i = 0; i < 2; i++)
#pragma unroll
        for (int j = 0; j < 8; j++)
#pragma unroll
            for (int k = 0; k < 4; k++) acc[i][j][k] = 0.f;

    auto prefetch = [&](int ch, int st) {
        int k2 = ch * 32;
#pragma unroll
        for (int i = 0; i < 4; i++) {
            int idx = tid + i * 256;
            int r = idx >> 3;
            int c2 = (idx & 7) * 4;
            int gr = rowBase + r;
            uint32_t adst = (uint32_t)__cvta_generic_to_shared(Abuf[st] + r * TPAD + c2);
            cp_async16(adst, g_xh + (size_t)gr * 512 + k2 + c2, gr < NN ? 16 : 0);
            uint32_t bdst = (uint32_t)__cvta_generic_to_shared(Bbuf[st] + r * TPAD + c2);
            cp_async16(bdst, g_pWh + (size_t)(colBase + r) * 512 + k2 + c2, 16);
        }
        CP_COMMIT();
    };

    prefetch(0, 0);
    for (int ch = 0; ch < 16; ch++) {
        int st = ch & 1;
        CP_WAIT0();
        __syncthreads();
        if (ch < 15) prefetch(ch + 1, st ^ 1);
        __half2* As = Abuf[st];
        __half2* Bs = Bbuf[st];
#pragma unroll
        for (int kk2 = 0; kk2 < 32; kk2 += 8) {
            uint32_t a[2][4];
#pragma unroll
            for (int ma = 0; ma < 2; ma++) {
                uint32_t addr = (uint32_t)__cvta_generic_to_shared(
                    As + (mRow + ma * 16 + (lt & 1) * 8 + li) * TPAD + kk2 + (lt >> 1) * 4);
                LDSM_X4(a[ma][0], a[ma][1], a[ma][2], a[ma][3], addr);
            }
            uint32_t b[8][2];
#pragma unroll
            for (int nb = 0; nb < 8; nb += 2) {
                uint32_t addr = (uint32_t)__cvta_generic_to_shared(
                    Bs + (nBase + nb * 8 + (lt >> 1) * 8 + li) * TPAD + kk2 + (lt & 1) * 4);
                uint32_t r0, r1, r2, r3;
                LDSM_X4(r0, r1, r2, r3, addr);
                b[nb][0] = r0; b[nb][1] = r1;
                b[nb + 1][0] = r2; b[nb + 1][1] = r3;
            }
#pragma unroll
            for (int nb = 0; nb < 8; nb++)
#pragma unroll
                for (int ma = 0; ma < 2; ma++)
                    MMA_F16(acc[ma][nb], a[ma][0], a[ma][1], a[ma][2], a[ma][3],
                            b[nb][0], b[nb][1]);
        }
        __syncthreads();
    }

#pragma unroll
    for (int ma = 0; ma < 2; ma++) {
        int r0 = rowBase + mRow + ma * 16 + quadRow;
        int r1 = r0 + 8;
#pragma unroll
        for (int nb = 0; nb < 8; nb++) {
            int c = colBase + nBase + nb * 8 + quadCol * 2;
            float bx = bias[c], by = bias[c + 1];
            if (r0 < NN)
                g_h0h[(size_t)r0 * 128 + (c >> 1)] =
                    __floats2half2_rn(acc[ma][nb][0] + bx, acc[ma][nb][1] + by);
            if (r1 < NN)
                g_h0h[(size_t)r1 * 128 + (c >> 1)] =
                    __floats2half2_rn(acc[ma][nb][2] + bx, acc[ma][nb][3] + by);
        }
    }
}

// ---------------- classifier (reads fp16 h) ----------------
__global__ void k_cls(const float* __restrict__ Wc, const float* __restrict__ bc,
                      float* __restrict__ out) {
    int gw   = (blockIdx.x * blockDim.x + threadIdx.x) >> 5;
    int lane = threadIdx.x & 31;
    if (gw >= NN) return;
    const __half2* hr = g_hh + (size_t)gw * 128;
    float a0 = 0.f, a1 = 0.f, a2 = 0.f, a3 = 0.f;
    for (int k2 = lane; k2 < 128; k2 += 32) {
        float2 hv = __half22float2(hr[k2]);
        const float* w0 = Wc + (k2 * 2) * CC;
        a0 = fmaf(hv.x, w0[0], a0); a1 = fmaf(hv.x, w0[1], a1);
        a2 = fmaf(hv.x, w0[2], a2); a3 = fmaf(hv.x, w0[3], a3);
        a0 = fmaf(hv.y, w0[4], a0); a1 = fmaf(hv.y, w0[5], a1);
        a2 = fmaf(hv.y, w0[6], a2); a3 = fmaf(hv.y, w0[7], a3);
    }
#pragma unroll
    for (int off = 16; off; off >>= 1) {
        a0 += __shfl_down_sync(0xffffffffu, a0, off);
        a1 += __shfl_down_sync(0xffffffffu, a1, off);
        a2 += __shfl_down_sync(0xffffffffu, a2, off);
        a3 += __shfl_down_sync(0xffffffffu, a3, off);
    }
    if (lane == 0) {
        out[gw * CC + 0] = a0 + bc[0];
        out[gw * CC + 1] = a1 + bc[1];
        out[gw * CC + 2] = a2 + bc[2];
        out[gw * CC + 3] = a3 + bc[3];
    }
}

// ---------------- launch ----------------

extern "C" void kernel_launch(void* const* d_in, const int* in_sizes, int n_in,
                              void* d_out, int out_size) {
    const float* x     = (const float*)d_in[0];
    const int*   ei    = (const int*)  d_in[1];
    const float* projW = (const float*)d_in[2];
    const float* projb = (const float*)d_in[3];
    const float* wts   = (const float*)d_in[4];
    const float* clsW  = (const float*)d_in[5];
    const float* clsb  = (const float*)d_in[6];
    float* out = (float*)d_out;

    const int* src = ei;
    const int* dst = ei + EE;

    static int attrDone = 0;
    if (!attrDone) {
        cudaFuncSetAttribute(k_gemm_mma, cudaFuncAttributeMaxDynamicSharedMemorySize, MMA_SMEM);
        cudaFuncSetAttribute(k_gemm_proj, cudaFuncAttributeMaxDynamicSharedMemorySize, GEMM_SMEM);
        attrDone = 1;
    }

    k_init_deg<<<(NN + 255) / 256, 256>>>();
    k_count   <<<(EE + 255) / 256, 256>>>(dst);
    k_dinv    <<<(NN + 255) / 256, 256>>>();
    k_scan    <<<1, 1024>>>();
    k_selfloop<<<(NN + 255) / 256, 256>>>();
    k_fill    <<<(EE + 255) / 256, 256>>>(src, dst);

    dim3 tg(HH / 32, HH / 32, LL);
    k_transpose_w<<<tg, dim3(32, 8)>>>(wts);
    dim3 pg(HH / 32, DIN / 32);
    k_transpose_pw<<<pg, dim3(32, 8)>>>(projW);
    k_x2h<<<(NN * DIN / 4 + 255) / 256, 256>>>(x);

    dim3 gg((NN + 127) / 128, 2);
    k_gemm_proj<<<gg, 256, GEMM_SMEM>>>(projb);

    int mGrid = (NN + 127) / 128;
    for (int l = 0; l < LL; l++) {
        k_spmm<<<NN, 128>>>(l == 0 ? 1 : 0);
        k_gemm_mma<<<mGrid, 512, MMA_SMEM>>>(l);
    }

    k_cls<<<(NN * 32 + 255) / 256, 256>>>(clsW, clsb, out);
}

// round 16
// speedup vs baseline: 3.0051x; 1.0207x over previous
#include <cuda_runtime.h>
#include <cuda_fp16.h>
#include <math.h>
#include <stdint.h>

#define NN   50000
#define EE   1600000
#define DIN  1024
#define HH   256
#define LL   64
#define CC   4
#define NNZ  (EE + NN)

// ---------------- scratch (device globals: no allocation allowed) ----------
__device__ __half2 g_hh [(size_t)NN * (HH / 2)];    // fp16 h
__device__ __half2 g_h0h[(size_t)NN * (HH / 2)];    // fp16 h0
__device__ __half2 g_sh [(size_t)NN * (HH / 2)];    // fp16 s
__device__ __half2 g_xh [(size_t)NN * (DIN / 2)];   // fp16 x
__device__ __half2 g_wTh[(size_t)LL * HH * (HH / 2)];  // fp16 W'^T = ((1-b)I + b W)^T
__device__ __half2 g_pWh[(size_t)HH * (DIN / 2)];
__device__ int     g_deg[NN];
__device__ float   g_dinv[NN];
__device__ int     g_rowptr[NN + 1];
__device__ int     g_fill[NN];
__device__ int     g_col[NNZ];
__device__ float   g_val[NNZ];

// ---------------- graph preprocessing ----------------

__global__ void k_init_deg() {
    int i = blockIdx.x * blockDim.x + threadIdx.x;
    if (i < NN) g_deg[i] = 1;
}
__global__ void k_count(const int* __restrict__ dst) {
    int e = blockIdx.x * blockDim.x + threadIdx.x;
    if (e < EE) atomicAdd(&g_deg[dst[e]], 1);
}
__global__ void k_dinv() {
    int i = blockIdx.x * blockDim.x + threadIdx.x;
    if (i < NN) g_dinv[i] = rsqrtf((float)g_deg[i]);
}
__global__ void k_scan() {
    __shared__ int sh[1024];
    __shared__ int carry;
    int tid = threadIdx.x;
    if (tid == 0) { carry = 0; g_rowptr[0] = 0; }
    __syncthreads();
    for (int base = 0; base < NN; base += 1024) {
        int i = base + tid;
        int v = (i < NN) ? g_deg[i] : 0;
        sh[tid] = v;
        __syncthreads();
        for (int off = 1; off < 1024; off <<= 1) {
            int t = (tid >= off) ? sh[tid - off] : 0;
            __syncthreads();
            sh[tid] += t;
            __syncthreads();
        }
        if (i < NN) g_rowptr[i + 1] = carry + sh[tid];
        __syncthreads();
        if (tid == 0) carry += sh[1023];
        __syncthreads();
    }
}
__global__ void k_selfloop() {
    int i = blockIdx.x * blockDim.x + threadIdx.x;
    if (i < NN) {
        int p = g_rowptr[i];
        float d = g_dinv[i];
        g_col[p] = i;
        g_val[p] = d * d;
        g_fill[i] = 1;
    }
}
__global__ void k_fill(const int* __restrict__ src, const int* __restrict__ dst) {
    int e = blockIdx.x * blockDim.x + threadIdx.x;
    if (e < EE) {
        int d = dst[e];
        int s = src[e];
        int p = atomicAdd(&g_fill[d], 1);
        int idx = g_rowptr[d] + p;
        g_col[idx] = s;
        g_val[idx] = g_dinv[s] * g_dinv[d];
    }
}

// weight transpose + residual fold: g_wTh[l][n][k] = fp16((1-b)I[k][n] + b*W[l][k][n])
__global__ void k_transpose_w(const float* __restrict__ W) {
    __shared__ float t[32][33];
    int l = blockIdx.z;
    float beta = logf(0.5f / (float)(l + 1) + 1.0f);
    int n0 = blockIdx.x * 32, k0 = blockIdx.y * 32;
    const float* Wl = W + (size_t)l * HH * HH;
    __half* out = reinterpret_cast<__half*>(g_wTh) + (size_t)l * HH * HH;
#pragma unroll
    for (int dy = 0; dy < 32; dy += 8)
        t[threadIdx.y + dy][threadIdx.x] = Wl[(size_t)(k0 + threadIdx.y + dy) * HH + n0 + threadIdx.x];
    __syncthreads();
#pragma unroll
    for (int dy = 0; dy < 32; dy += 8) {
        int n = n0 + threadIdx.y + dy;
        int k = k0 + threadIdx.x;
        float v = beta * t[threadIdx.x][threadIdx.y + dy];
        if (n == k) v += 1.0f - beta;
        out[(size_t)n * HH + k] = __float2half_rn(v);
    }
}

// projW transpose to fp16
__global__ void k_transpose_pw(const float* __restrict__ PW) {
    __shared__ float t[32][33];
    int n0 = blockIdx.x * 32, k0 = blockIdx.y * 32;
    __half* out = reinterpret_cast<__half*>(g_pWh);
#pragma unroll
    for (int dy = 0; dy < 32; dy += 8)
        t[threadIdx.y + dy][threadIdx.x] = PW[(size_t)(k0 + threadIdx.y + dy) * HH + n0 + threadIdx.x];
    __syncthreads();
#pragma unroll
    for (int dy = 0; dy < 32; dy += 8)
        out[(size_t)(n0 + threadIdx.y + dy) * DIN + k0 + threadIdx.x] =
            __float2half_rn(t[threadIdx.x][threadIdx.y + dy]);
}

// x -> fp16
__global__ void k_x2h(const float* __restrict__ x) {
    int i = blockIdx.x * blockDim.x + threadIdx.x;
    const int total = NN * DIN / 4;
    if (i < total) {
        float4 v = reinterpret_cast<const float4*>(x)[i];
        g_xh[i * 2 + 0] = __floats2half2_rn(v.x, v.y);
        g_xh[i * 2 + 1] = __floats2half2_rn(v.z, v.w);
    }
}

// ---------------- SpMM: s_fp16 = 0.8 * (A_hat @ h) + 0.2 * h0 (all fp16) ----
__global__ __launch_bounds__(128) void k_spmm(int first) {
    const __half2* __restrict__ hin = first ? g_h0h : g_hh;
    int row = blockIdx.x;
    int tid = threadIdx.x;
    int s0 = g_rowptr[row];
    int s1 = g_rowptr[row + 1];
    __shared__ int   scol[64];
    __shared__ float sval[64];
    float accx = 0.f, accy = 0.f;
    for (int e0 = s0; e0 < s1; e0 += 64) {
        int nE = min(64, s1 - e0);
        __syncthreads();
        if (tid < nE) { scol[tid] = g_col[e0 + tid]; sval[tid] = g_val[e0 + tid]; }
        __syncthreads();
        int i = 0;
        for (; i + 4 <= nE; i += 4) {
            float2 f0 = __half22float2(hin[(size_t)scol[i + 0] * 128 + tid]);
            float2 f1 = __half22float2(hin[(size_t)scol[i + 1] * 128 + tid]);
            float2 f2 = __half22float2(hin[(size_t)scol[i + 2] * 128 + tid]);
            float2 f3 = __half22float2(hin[(size_t)scol[i + 3] * 128 + tid]);
            accx = fmaf(sval[i + 0], f0.x, accx); accy = fmaf(sval[i + 0], f0.y, accy);
            accx = fmaf(sval[i + 1], f1.x, accx); accy = fmaf(sval[i + 1], f1.y, accy);
            accx = fmaf(sval[i + 2], f2.x, accx); accy = fmaf(sval[i + 2], f2.y, accy);
            accx = fmaf(sval[i + 3], f3.x, accx); accy = fmaf(sval[i + 3], f3.y, accy);
        }
        for (; i < nE; i++) {
            float2 f = __half22float2(hin[(size_t)scol[i] * 128 + tid]);
            accx = fmaf(sval[i], f.x, accx);
            accy = fmaf(sval[i], f.y, accy);
        }
    }
    float2 h0v = __half22float2(g_h0h[(size_t)row * 128 + tid]);
    g_sh[(size_t)row * 128 + tid] =
        __floats2half2_rn(0.8f * accx + 0.2f * h0v.x, 0.8f * accy + 0.2f * h0v.y);
}

// ---------------- MMA / async helpers ----------------

#define MMA_F16(ACC, A0, A1, A2, A3, B0, B1)                                 \
    asm volatile(                                                            \
        "mma.sync.aligned.m16n8k16.row.col.f32.f16.f16.f32 "                \
        "{%0,%1,%2,%3}, {%4,%5,%6,%7}, {%8,%9}, {%0,%1,%2,%3};"             \
        : "+f"((ACC)[0]), "+f"((ACC)[1]), "+f"((ACC)[2]), "+f"((ACC)[3])    \
        : "r"(A0), "r"(A1), "r"(A2), "r"(A3), "r"(B0), "r"(B1))

#define LDSM_X4(R0, R1, R2, R3, ADDR)                                        \
    asm volatile(                                                            \
        "ldmatrix.sync.aligned.m8n8.x4.shared.b16 {%0,%1,%2,%3}, [%4];"     \
        : "=r"(R0), "=r"(R1), "=r"(R2), "=r"(R3) : "r"(ADDR))

__device__ __forceinline__ void cp_async16(uint32_t saddr, const void* g, int srcBytes) {
    asm volatile("cp.async.ca.shared.global [%0], [%1], 16, %2;"
                 :: "r"(saddr), "l"(g), "r"(srcBytes) : "memory");
}
#define CP_COMMIT() asm volatile("cp.async.commit_group;" ::: "memory")
#define CP_WAIT0()  asm volatile("cp.async.wait_group 0;" ::: "memory")

#define TPAD 36
#define EPAD 132                           // epilogue tile padded stride (h2)
#define A_ST (128 * TPAD)
#define B_ST (256 * TPAD)
#define MMA_SMEM ((2 * A_ST + 2 * B_ST) * 4)   // 110592 B (>= 128*EPAD*4 = 67584)

// layer GEMM single-slab: h = relu(s @ W'), full N=256 per CTA.
// 512 threads, 16 warps (4x4), warp tile 32x64, 4 K-chunks, pipelined.
// Epilogue staged through SMEM -> coalesced float4 stores.
__global__ __launch_bounds__(512, 1) void k_gemm_mma(int layer) {
    extern __shared__ __half2 dsm[];
    __half2* Abuf[2] = { dsm, dsm + A_ST };
    __half2* Bbuf[2] = { dsm + 2 * A_ST, dsm + 2 * A_ST + B_ST };

    const __half2* __restrict__ wTl = g_wTh + (size_t)layer * HH * 128;

    int tid = threadIdx.x;
    int wid = tid >> 5;
    int lane = tid & 31;
    int quadRow = lane >> 2;
    int quadCol = lane & 3;
    int warpM = wid >> 2;          // 0..3
    int warpN = wid & 3;           // 0..3
    int mRow = warpM * 32;
    int nBase = warpN * 64;
    int rowBase = blockIdx.x * 128;
    int lt = lane >> 3;
    int li = lane & 7;

    float acc[2][8][4];
#pragma unroll
    for (int i = 0; i < 2; i++)
#pragma unroll
        for (int j = 0; j < 8; j++)
#pragma unroll
            for (int k = 0; k < 4; k++) acc[i][j][k] = 0.f;

    auto prefetch = [&](int ch, int st) {
        int k2 = ch * 32;
#pragma unroll
        for (int i = 0; i < 2; i++) {
            int idx = tid + i * 512;
            int r = idx >> 3;
            int c2 = (idx & 7) * 4;
            int gr = rowBase + r;
            uint32_t adst = (uint32_t)__cvta_generic_to_shared(Abuf[st] + r * TPAD + c2);
            cp_async16(adst, g_sh + (size_t)gr * 128 + k2 + c2, gr < NN ? 16 : 0);
        }
#pragma unroll
        for (int i = 0; i < 4; i++) {
            int idx = tid + i * 512;
            int r = idx >> 3;
            int c2 = (idx & 7) * 4;
            uint32_t bdst = (uint32_t)__cvta_generic_to_shared(Bbuf[st] + r * TPAD + c2);
            cp_async16(bdst, wTl + (size_t)r * 128 + k2 + c2, 16);
        }
        CP_COMMIT();
    };

    prefetch(0, 0);
    for (int ch = 0; ch < 4; ch++) {
        int st = ch & 1;
        CP_WAIT0();
        __syncthreads();
        if (ch < 3) prefetch(ch + 1, st ^ 1);
        __half2* As = Abuf[st];
        __half2* Bs = Bbuf[st];
#pragma unroll
        for (int kk2 = 0; kk2 < 32; kk2 += 8) {
            uint32_t a[2][4];
#pragma unroll
            for (int ma = 0; ma < 2; ma++) {
                uint32_t addr = (uint32_t)__cvta_generic_to_shared(
                    As + (mRow + ma * 16 + (lt & 1) * 8 + li) * TPAD + kk2 + (lt >> 1) * 4);
                LDSM_X4(a[ma][0], a[ma][1], a[ma][2], a[ma][3], addr);
            }
            uint32_t b[8][2];
#pragma unroll
            for (int nb = 0; nb < 8; nb += 2) {
                uint32_t addr = (uint32_t)__cvta_generic_to_shared(
                    Bs + (nBase + nb * 8 + (lt >> 1) * 8 + li) * TPAD + kk2 + (lt & 1) * 4);
                uint32_t r0, r1, r2, r3;
                LDSM_X4(r0, r1, r2, r3, addr);
                b[nb][0] = r0; b[nb][1] = r1;
                b[nb + 1][0] = r2; b[nb + 1][1] = r3;
            }
#pragma unroll
            for (int nb = 0; nb < 8; nb++)
#pragma unroll
                for (int ma = 0; ma < 2; ma++)
                    MMA_F16(acc[ma][nb], a[ma][0], a[ma][1], a[ma][2], a[ma][3],
                            b[nb][0], b[nb][1]);
        }
        __syncthreads();
    }

    // ---- epilogue: relu -> SMEM tile -> coalesced float4 stores ----
    __half2* Etile = dsm;   // buffers dead after last sync; 128*EPAD h2
#pragma unroll
    for (int ma = 0; ma < 2; ma++) {
        int rl0 = mRow + ma * 16 + quadRow;
        int rl1 = rl0 + 8;
#pragma unroll
        for (int nb = 0; nb < 8; nb++) {
            int c2 = (nBase + nb * 8 + quadCol * 2) >> 1;
            Etile[rl0 * EPAD + c2] = __floats2half2_rn(
                fmaxf(acc[ma][nb][0], 0.f), fmaxf(acc[ma][nb][1], 0.f));
            Etile[rl1 * EPAD + c2] = __floats2half2_rn(
                fmaxf(acc[ma][nb][2], 0.f), fmaxf(acc[ma][nb][3], 0.f));
        }
    }
    __syncthreads();
#pragma unroll
    for (int i = 0; i < 8; i++) {
        int idx = tid + i * 512;       // 0..4095
        int r = idx >> 5;              // 0..127
        int c4 = idx & 31;             // float4 column (4 h2 each)
        int grow = rowBase + r;
        if (grow < NN) {
            float4 v = *reinterpret_cast<float4*>(Etile + r * EPAD + c4 * 4);
            *reinterpret_cast<float4*>(g_hh + (size_t)grow * 128 + c4 * 4) = v;
        }
    }
}

// ---------------- projection GEMM fp16 (pipelined, 256 threads) -----

#define STAGE_H2 (128 * TPAD)
#define GEMM_SMEM (4 * STAGE_H2 * 4)   // 73728 (>= 67584 for epilogue tile)

__global__ __launch_bounds__(256, 2) void k_gemm_proj(const float* __restrict__ bias) {
    extern __shared__ __half2 dsm[];
    __half2* Abuf[2] = { dsm, dsm + STAGE_H2 };
    __half2* Bbuf[2] = { dsm + 2 * STAGE_H2, dsm + 3 * STAGE_H2 };

    int tid = threadIdx.x;
    int wid = tid >> 5;
    int lane = tid & 31;
    int quadRow = lane >> 2;
    int quadCol = lane & 3;
    int warpM = wid >> 1;
    int warpN = wid & 1;
    int mRow = warpM * 32;
    int nBase = warpN * 64;
    int rowBase = blockIdx.x * 128;
    int colBase = blockIdx.y * 128;

    int lt = lane >> 3;
    int li = lane & 7;

    float acc[2][8][4];
#pragma unroll
    for (int i = 0; i < 2; i++)
#pragma unroll
        for (int j = 0; j < 8; j++)
#pragma unroll
            for (int k = 0; k < 4; k++) acc[i][j][k] = 0.f;

    auto prefetch = [&](int ch, int st) {
        int k2 = ch * 32;
#pragma unroll
        for (int i = 0; i < 4; i++) {
            int idx = tid + i * 256;
            int r = idx >> 3;
            int c2 = (idx & 7) * 4;
            int gr = rowBase + r;
            uint32_t adst = (uint32_t)__cvta_generic_to_shared(Abuf[st] + r * TPAD + c2);
            cp_async16(adst, g_xh + (size_t)gr * 512 + k2 + c2, gr < NN ? 16 : 0);
            uint32_t bdst = (uint32_t)__cvta_generic_to_shared(Bbuf[st] + r * TPAD + c2);
            cp_async16(bdst, g_pWh + (size_t)(colBase + r) * 512 + k2 + c2, 16);
        }
        CP_COMMIT();
    };

    prefetch(0, 0);
    for (int ch = 0; ch < 16; ch++) {
        int st = ch & 1;
        CP_WAIT0();
        __syncthreads();
        if (ch < 15) prefetch(ch + 1, st ^ 1);
        __half2* As = Abuf[st];
        __half2* Bs = Bbuf[st];
#pragma unroll
        for (int kk2 = 0; kk2 < 32; kk2 += 8) {
            uint32_t a[2][4];
#pragma unroll
            for (int ma = 0; ma < 2; ma++) {
                uint32_t addr = (uint32_t)__cvta_generic_to_shared(
                    As + (mRow + ma * 16 + (lt & 1) * 8 + li) * TPAD + kk2 + (lt >> 1) * 4);
                LDSM_X4(a[ma][0], a[ma][1], a[ma][2], a[ma][3], addr);
            }
            uint32_t b[8][2];
#pragma unroll
            for (int nb = 0; nb < 8; nb += 2) {
                uint32_t addr = (uint32_t)__cvta_generic_to_shared(
                    Bs + (nBase + nb * 8 + (lt >> 1) * 8 + li) * TPAD + kk2 + (lt & 1) * 4);
                uint32_t r0, r1, r2, r3;
                LDSM_X4(r0, r1, r2, r3, addr);
                b[nb][0] = r0; b[nb][1] = r1;
                b[nb + 1][0] = r2; b[nb + 1][1] = r3;
            }
#pragma unroll
            for (int nb = 0; nb < 8; nb++)
#pragma unroll
                for (int ma = 0; ma < 2; ma++)
                    MMA_F16(acc[ma][nb], a[ma][0], a[ma][1], a[ma][2], a[ma][3],
                            b[nb][0], b[nb][1]);
        }
        __syncthreads();
    }

    // ---- epilogue: +bias -> SMEM tile (128 x 128 h2, this CTA's slab) ----
    __half2* Etile = dsm;
#pragma unroll
    for (int ma = 0; ma < 2; ma++) {
        int rl0 = mRow + ma * 16 + quadRow;
        int rl1 = rl0 + 8;
#pragma unroll
        for (int nb = 0; nb < 8; nb++) {
            int cl = nBase + nb * 8 + quadCol * 2;      // local col in slab
            int cg = colBase + cl;
            float bx = bias[cg], by = bias[cg + 1];
            Etile[rl0 * EPAD + (cl >> 1)] =
                __floats2half2_rn(acc[ma][nb][0] + bx, acc[ma][nb][1] + by);
            Etile[rl1 * EPAD + (cl >> 1)] =
                __floats2half2_rn(acc[ma][nb][2] + bx, acc[ma][nb][3] + by);
        }
    }
    __syncthreads();
    // slab is 128 h2 wide? NO: this CTA covers 128 cols = 64 h2.
    // 128 rows x 64 h2 = 8192 h2 = 2048 float4; 256 threads x 8 each.
#pragma unroll
    for (int i = 0; i < 8; i++) {
        int idx = tid + i * 256;       // 0..2047
        int r = idx >> 4;              // 0..127 (16 float4 per row)
        int c4 = idx & 15;
        int grow = rowBase + r;
        if (grow < NN) {
            float4 v = *reinterpret_cast<float4*>(Etile + r * EPAD + c4 * 4);
            *reinterpret_cast<float4*>(g_h0h + (size_t)grow * 128 + (colBase >> 1) + c4 * 4) = v;
        }
    }
}

// ---------------- classifier (reads fp16 h) ----------------
__global__ void k_cls(const float* __restrict__ Wc, const float* __restrict__ bc,
                      float* __restrict__ out) {
    int gw   = (blockIdx.x * blockDim.x + threadIdx.x) >> 5;
    int lane = threadIdx.x & 31;
    if (gw >= NN) return;
    const __half2* hr = g_hh + (size_t)gw * 128;
    float a0 = 0.f, a1 = 0.f, a2 = 0.f, a3 = 0.f;
    for (int k2 = lane; k2 < 128; k2 += 32) {
        float2 hv = __half22float2(hr[k2]);
        const float* w0 = Wc + (k2 * 2) * CC;
        a0 = fmaf(hv.x, w0[0], a0); a1 = fmaf(hv.x, w0[1], a1);
        a2 = fmaf(hv.x, w0[2], a2); a3 = fmaf(hv.x, w0[3], a3);
        a0 = fmaf(hv.y, w0[4], a0); a1 = fmaf(hv.y, w0[5], a1);
        a2 = fmaf(hv.y, w0[6], a2); a3 = fmaf(hv.y, w0[7], a3);
    }
#pragma unroll
    for (int off = 16; off; off >>= 1) {
        a0 += __shfl_down_sync(0xffffffffu, a0, off);
        a1 += __shfl_down_sync(0xffffffffu, a1, off);
        a2 += __shfl_down_sync(0xffffffffu, a2, off);
        a3 += __shfl_down_sync(0xffffffffu, a3, off);
    }
    if (lane == 0) {
        out[gw * CC + 0] = a0 + bc[0];
        out[gw * CC + 1] = a1 + bc[1];
        out[gw * CC + 2] = a2 + bc[2];
        out[gw * CC + 3] = a3 + bc[3];
    }
}

// ---------------- launch ----------------

extern "C" void kernel_launch(void* const* d_in, const int* in_sizes, int n_in,
                              void* d_out, int out_size) {
    const float* x     = (const float*)d_in[0];
    const int*   ei    = (const int*)  d_in[1];
    const float* projW = (const float*)d_in[2];
    const float* projb = (const float*)d_in[3];
    const float* wts   = (const float*)d_in[4];
    const float* clsW  = (const float*)d_in[5];
    const float* clsb  = (const float*)d_in[6];
    float* out = (float*)d_out;

    const int* src = ei;
    const int* dst = ei + EE;

    static int attrDone = 0;
    if (!attrDone) {
        cudaFuncSetAttribute(k_gemm_mma, cudaFuncAttributeMaxDynamicSharedMemorySize, MMA_SMEM);
        cudaFuncSetAttribute(k_gemm_proj, cudaFuncAttributeMaxDynamicSharedMemorySize, GEMM_SMEM);
        attrDone = 1;
    }

    k_init_deg<<<(NN + 255) / 256, 256>>>();
    k_count   <<<(EE + 255) / 256, 256>>>(dst);
    k_dinv    <<<(NN + 255) / 256, 256>>>();
    k_scan    <<<1, 1024>>>();
    k_selfloop<<<(NN + 255) / 256, 256>>>();
    k_fill    <<<(EE + 255) / 256, 256>>>(src, dst);

    dim3 tg(HH / 32, HH / 32, LL);
    k_transpose_w<<<tg, dim3(32, 8)>>>(wts);
    dim3 pg(HH / 32, DIN / 32);
    k_transpose_pw<<<pg, dim3(32, 8)>>>(projW);
    k_x2h<<<(NN * DIN / 4 + 255) / 256, 256>>>(x);

    dim3 gg((NN + 127) / 128, 2);
    k_gemm_proj<<<gg, 256, GEMM_SMEM>>>(projb);

    int mGrid = (NN + 127) / 128;
    for (int l = 0; l < LL; l++) {
        k_spmm<<<NN, 128>>>(l == 0 ? 1 : 0);
        k_gemm_mma<<<mGrid, 512, MMA_SMEM>>>(l);
    }

    k_cls<<<(NN * 32 + 255) / 256, 256>>>(clsW, clsb, out);
}